// round 15
// baseline (speedup 1.0000x reference)
#include <cuda_runtime.h>
#include <cuda_bf16.h>
#include <cstdint>

#define DT_F      0.1f
#define PI_F      3.14159265358979323846f
#define TWO_PI_F  6.28318530717958647692f

#define NTHREADS       128
#define ROWS_PER_BLOCK 256                       // 2 rows per thread: tid and tid+128
#define X_FLOATS       (ROWS_PER_BLOCK * 5)      // 1280 floats = 5120 B
#define XH_FLOATS      (X_FLOATS / 2)            // 640 floats = 2560 B per half
#define XH_BYTES       (XH_FLOATS * 4)

__device__ __forceinline__ uint32_t smem_u32(const void* p) {
    uint32_t a;
    asm("{ .reg .u64 t; cvta.to.shared.u64 t, %1; cvt.u32.u64 %0, t; }" : "=r"(a) : "l"(p));
    return a;
}

__device__ __forceinline__ void mbar_wait(uint32_t mb) {
    asm volatile(
        "{\n\t.reg .pred P;\n\t"
        "W_%=:\n\t"
        "mbarrier.try_wait.parity.acquire.cta.shared::cta.b64 P, [%0], 0, 0x989680;\n\t"
        "@P bra D_%=;\n\t"
        "bra W_%=;\n\t"
        "D_%=:\n\t}"
        :: "r"(mb) : "memory");
}

__global__ void __launch_bounds__(NTHREADS, 16) Model_72026601554419_kernel(
    const float*  __restrict__ x_g,
    const float2* __restrict__ a_g2,
    const float2* __restrict__ n_g2,
    const float*  __restrict__ pro_gains,
    const float*  __restrict__ pro_noise_ln_vars,
    const float*  __restrict__ goal_radius,
    float*        __restrict__ outx_g,
    float*        __restrict__ outf_g)
{
    __shared__ __align__(128) float sx[X_FLOATS];    // x slab, reused in-place for output
    __shared__ __align__(8)   uint64_t mbar[2];      // one per x half-tile

    const int    tid = threadIdx.x;
    const size_t blk = blockIdx.x;
    const float* xg  = x_g + blk * X_FLOATS;

    const uint32_t mbA = smem_u32(&mbar[0]);
    const uint32_t mbB = smem_u32(&mbar[1]);

    if (tid == 0) {
        asm volatile("mbarrier.init.shared::cta.b64 [%0], 1;" :: "r"(mbA) : "memory");
        asm volatile("mbarrier.init.shared::cta.b64 [%0], 1;" :: "r"(mbB) : "memory");
    }
    __syncthreads();   // mbarriers visible before issue/poll

    // Issue both x half-tile loads immediately; half A completes first,
    // letting compute start after ~half the tile latency.
    if (tid == 0) {
        asm volatile("mbarrier.arrive.expect_tx.shared::cta.b64 _, [%0], %1;"
                     :: "r"(mbA), "r"((uint32_t)XH_BYTES) : "memory");
        asm volatile("cp.async.bulk.shared::cluster.global.mbarrier::complete_tx::bytes "
                     "[%0], [%1], %2, [%3];"
                     :: "r"(smem_u32(sx)), "l"(xg), "r"((uint32_t)XH_BYTES), "r"(mbA) : "memory");
        asm volatile("mbarrier.arrive.expect_tx.shared::cta.b64 _, [%0], %1;"
                     :: "r"(mbB), "r"((uint32_t)XH_BYTES) : "memory");
        asm volatile("cp.async.bulk.shared::cluster.global.mbarrier::complete_tx::bytes "
                     "[%0], [%1], %2, [%3];"
                     :: "r"(smem_u32(sx + XH_FLOATS)), "l"(xg + XH_FLOATS),
                        "r"((uint32_t)XH_BYTES), "r"(mbB) : "memory");
    }

    // a/noise: direct coalesced LDG.64 (lane i -> consecutive float2), issued
    // before any wait so they overlap the x TMA. 4 independent loads = MLP 4.
    const size_t rowbase = blk * ROWS_PER_BLOCK + tid;
    const float2 arA = a_g2[rowbase];
    const float2 nrA = n_g2[rowbase];
    const float2 arB = a_g2[rowbase + NTHREADS];
    const float2 nrB = n_g2[rowbase + NTHREADS];

    const float g0  = __ldg(pro_gains);
    const float g1  = __ldg(pro_gains + 1);
    const float s0  = __expf(0.5f * __ldg(pro_noise_ln_vars));      // sqrt(exp(v))
    const float s1  = __expf(0.5f * __ldg(pro_noise_ln_vars + 1));
    const float grv = __ldg(goal_radius);

#pragma unroll
    for (int half = 0; half < 2; half++) {
        mbar_wait(half ? mbB : mbA);

        const int    r  = tid + half * NTHREADS;   // row at word 5r: stride 5 (odd) -> conflict-free
        const float2 ar = half ? arB : arA;
        const float2 nr = half ? nrB : nrA;

        float px  = sx[5 * r + 0];
        float py  = sx[5 * r + 1];
        float ang = sx[5 * r + 2];

        // Match reference op order/rounding (no FMA contraction)
        float vel     = __fadd_rn(__fmul_rn(g0, ar.x), __fmul_rn(s0, nr.x));
        float ang_vel = __fadd_rn(__fmul_rn(g1, ar.y), __fmul_rn(s1, nr.y));

        // range_angle: mod(ang + ang_vel*DT + pi, 2pi) - pi  (jnp.mod semantics)
        float an = __fadd_rn(__fadd_rn(ang, __fmul_rn(ang_vel, DT_F)), PI_F);
        an = fmodf(an, TWO_PI_F);
        if (an < 0.0f) an += TWO_PI_F;
        an -= PI_F;

        float sn_v, cs_v;
        sincosf(an, &sn_v, &cs_v);

        px = fminf(fmaxf(__fadd_rn(px, __fmul_rn(__fmul_rn(vel, cs_v), DT_F)), -1.0f), 1.0f);
        py = fminf(fmaxf(__fadd_rn(py, __fmul_rn(__fmul_rn(vel, sn_v), DT_F)), -1.0f), 1.0f);

        sx[5 * r + 0] = px;
        sx[5 * r + 1] = py;
        sx[5 * r + 2] = an;
        sx[5 * r + 3] = vel;
        sx[5 * r + 4] = ang_vel;

        // Flags: direct coalesced scalar store (unit lane stride)
        const float d2 = __fadd_rn(__fmul_rn(px, px), __fmul_rn(py, py));
        outf_g[rowbase + half * NTHREADS] = (sqrtf(d2) <= grv) ? 1.0f : 0.0f;

        // Early half-A store: rows 0..127 (words 0..639) are complete across
        // all threads after this barrier; the 2.5KB store drains while half B
        // is still waiting/computing.
        __syncthreads();
        if (half == 0 && tid == 0) {
            asm volatile("fence.proxy.async.shared::cta;" ::: "memory");
            asm volatile("cp.async.bulk.global.shared::cta.bulk_group [%0], [%1], %2;"
                         :: "l"(outx_g + blk * X_FLOATS), "r"(smem_u32(sx)),
                            "r"((uint32_t)XH_BYTES) : "memory");
            asm volatile("cp.async.bulk.commit_group;" ::: "memory");
        }
    }

    if (tid == 0) {
        asm volatile("fence.proxy.async.shared::cta;" ::: "memory");
        asm volatile("cp.async.bulk.global.shared::cta.bulk_group [%0], [%1], %2;"
                     :: "l"(outx_g + blk * X_FLOATS + XH_FLOATS),
                        "r"(smem_u32(sx + XH_FLOATS)),
                        "r"((uint32_t)XH_BYTES) : "memory");
        asm volatile("cp.async.bulk.commit_group;" ::: "memory");
        // Only smem-read completion needed for safe retirement (both groups).
        asm volatile("cp.async.bulk.wait_group.read 0;" ::: "memory");
    }
}

extern "C" void kernel_launch(void* const* d_in, const int* in_sizes, int n_in,
                              void* d_out, int out_size)
{
    const float* x     = (const float*)d_in[0];  // [B,5]
    const float* a     = (const float*)d_in[1];  // [B,2]
    const float* noise = (const float*)d_in[2];  // [B,2]
    const float* pg    = (const float*)d_in[3];  // [2]
    const float* pv    = (const float*)d_in[4];  // [2]
    const float* gr    = (const float*)d_in[5];  // [1]

    const int B = in_sizes[0] / 5;               // 8388608 (divisible by 256)
    float* out      = (float*)d_out;             // [B*5] next_x
    float* out_flag = out + (size_t)B * 5;       // [B] reached_target as 0/1 float

    const int blocks = B / ROWS_PER_BLOCK;       // 32768

    Model_72026601554419_kernel<<<blocks, NTHREADS>>>(
        x, (const float2*)a, (const float2*)noise, pg, pv, gr, out, out_flag);
}

// round 16
// speedup vs baseline: 1.0164x; 1.0164x over previous
#include <cuda_runtime.h>
#include <cuda_bf16.h>
#include <cstdint>

#define DT_F      0.1f
#define PI_F      3.14159265358979323846f
#define TWO_PI_F  6.28318530717958647692f

#define NTHREADS       128
#define ROWS_PER_BLOCK 256                       // 2 rows per thread: tid and tid+128
#define X_FLOATS       (ROWS_PER_BLOCK * 5)      // 1280 floats = 5120 B
#define XH_FLOATS      (X_FLOATS / 2)            // 640 floats = 2560 B per half
#define XH_BYTES       (XH_FLOATS * 4)

__device__ __forceinline__ uint32_t smem_u32(const void* p) {
    uint32_t a;
    asm("{ .reg .u64 t; cvta.to.shared.u64 t, %1; cvt.u32.u64 %0, t; }" : "=r"(a) : "l"(p));
    return a;
}

__device__ __forceinline__ void mbar_wait(uint32_t mb) {
    asm volatile(
        "{\n\t.reg .pred P;\n\t"
        "W_%=:\n\t"
        "mbarrier.try_wait.parity.acquire.cta.shared::cta.b64 P, [%0], 0, 0x989680;\n\t"
        "@P bra D_%=;\n\t"
        "bra W_%=;\n\t"
        "D_%=:\n\t}"
        :: "r"(mb) : "memory");
}

__global__ void __launch_bounds__(NTHREADS, 16) Model_72026601554419_kernel(
    const float*  __restrict__ x_g,
    const float2* __restrict__ a_g2,
    const float2* __restrict__ n_g2,
    const float*  __restrict__ pro_gains,
    const float*  __restrict__ pro_noise_ln_vars,
    const float*  __restrict__ goal_radius,
    float*        __restrict__ outx_g,
    float*        __restrict__ outf_g)
{
    __shared__ __align__(128) float sx[X_FLOATS];    // x slab, reused in-place for output
    __shared__ __align__(8)   uint64_t mbar[2];      // one per x half-tile

    const int    tid = threadIdx.x;
    const size_t blk = blockIdx.x;
    const float* xg  = x_g + blk * X_FLOATS;

    const uint32_t mbA = smem_u32(&mbar[0]);
    const uint32_t mbB = smem_u32(&mbar[1]);

    if (tid == 0) {
        asm volatile("mbarrier.init.shared::cta.b64 [%0], 1;" :: "r"(mbA) : "memory");
        asm volatile("mbarrier.init.shared::cta.b64 [%0], 1;" :: "r"(mbB) : "memory");
    }
    __syncthreads();   // mbarriers visible before issue/poll

    // Issue both x half-tile loads immediately; half A completes first,
    // letting compute start after ~half the tile latency.
    if (tid == 0) {
        asm volatile("mbarrier.arrive.expect_tx.shared::cta.b64 _, [%0], %1;"
                     :: "r"(mbA), "r"((uint32_t)XH_BYTES) : "memory");
        asm volatile("cp.async.bulk.shared::cluster.global.mbarrier::complete_tx::bytes "
                     "[%0], [%1], %2, [%3];"
                     :: "r"(smem_u32(sx)), "l"(xg), "r"((uint32_t)XH_BYTES), "r"(mbA) : "memory");
        asm volatile("mbarrier.arrive.expect_tx.shared::cta.b64 _, [%0], %1;"
                     :: "r"(mbB), "r"((uint32_t)XH_BYTES) : "memory");
        asm volatile("cp.async.bulk.shared::cluster.global.mbarrier::complete_tx::bytes "
                     "[%0], [%1], %2, [%3];"
                     :: "r"(smem_u32(sx + XH_FLOATS)), "l"(xg + XH_FLOATS),
                        "r"((uint32_t)XH_BYTES), "r"(mbB) : "memory");
    }

    // a/noise: direct coalesced LDG.64 (lane i -> consecutive float2), issued
    // before any wait so they overlap the x TMA. 4 independent loads = MLP 4.
    const size_t rowbase = blk * ROWS_PER_BLOCK + tid;
    const float2 arA = a_g2[rowbase];
    const float2 nrA = n_g2[rowbase];
    const float2 arB = a_g2[rowbase + NTHREADS];
    const float2 nrB = n_g2[rowbase + NTHREADS];

    const float g0  = __ldg(pro_gains);
    const float g1  = __ldg(pro_gains + 1);
    const float s0  = __expf(0.5f * __ldg(pro_noise_ln_vars));      // sqrt(exp(v))
    const float s1  = __expf(0.5f * __ldg(pro_noise_ln_vars + 1));
    const float grv = __ldg(goal_radius);

#pragma unroll
    for (int half = 0; half < 2; half++) {
        mbar_wait(half ? mbB : mbA);

        const int    r  = tid + half * NTHREADS;   // row at word 5r: stride 5 (odd) -> conflict-free
        const float2 ar = half ? arB : arA;
        const float2 nr = half ? nrB : nrA;

        float px  = sx[5 * r + 0];
        float py  = sx[5 * r + 1];
        float ang = sx[5 * r + 2];

        // Match reference op order/rounding (no FMA contraction)
        float vel     = __fadd_rn(__fmul_rn(g0, ar.x), __fmul_rn(s0, nr.x));
        float ang_vel = __fadd_rn(__fmul_rn(g1, ar.y), __fmul_rn(s1, nr.y));

        // range_angle: mod(ang + ang_vel*DT + pi, 2pi) - pi  (jnp.mod semantics)
        float an = __fadd_rn(__fadd_rn(ang, __fmul_rn(ang_vel, DT_F)), PI_F);
        an = fmodf(an, TWO_PI_F);
        if (an < 0.0f) an += TWO_PI_F;
        an -= PI_F;

        float sn_v, cs_v;
        sincosf(an, &sn_v, &cs_v);

        px = fminf(fmaxf(__fadd_rn(px, __fmul_rn(__fmul_rn(vel, cs_v), DT_F)), -1.0f), 1.0f);
        py = fminf(fmaxf(__fadd_rn(py, __fmul_rn(__fmul_rn(vel, sn_v), DT_F)), -1.0f), 1.0f);

        sx[5 * r + 0] = px;
        sx[5 * r + 1] = py;
        sx[5 * r + 2] = an;
        sx[5 * r + 3] = vel;
        sx[5 * r + 4] = ang_vel;

        // Flags: direct coalesced scalar store (unit lane stride)
        const float d2 = __fadd_rn(__fmul_rn(px, px), __fmul_rn(py, py));
        outf_g[rowbase + half * NTHREADS] = (sqrtf(d2) <= grv) ? 1.0f : 0.0f;

        // Early half-A store: rows 0..127 (words 0..639) are complete across
        // all threads after this barrier; the 2.5KB store drains while half B
        // is still waiting/computing.
        __syncthreads();
        if (half == 0 && tid == 0) {
            asm volatile("fence.proxy.async.shared::cta;" ::: "memory");
            asm volatile("cp.async.bulk.global.shared::cta.bulk_group [%0], [%1], %2;"
                         :: "l"(outx_g + blk * X_FLOATS), "r"(smem_u32(sx)),
                            "r"((uint32_t)XH_BYTES) : "memory");
            asm volatile("cp.async.bulk.commit_group;" ::: "memory");
        }
    }

    if (tid == 0) {
        asm volatile("fence.proxy.async.shared::cta;" ::: "memory");
        asm volatile("cp.async.bulk.global.shared::cta.bulk_group [%0], [%1], %2;"
                     :: "l"(outx_g + blk * X_FLOATS + XH_FLOATS),
                        "r"(smem_u32(sx + XH_FLOATS)),
                        "r"((uint32_t)XH_BYTES) : "memory");
        asm volatile("cp.async.bulk.commit_group;" ::: "memory");
        // Only smem-read completion needed for safe retirement (both groups).
        asm volatile("cp.async.bulk.wait_group.read 0;" ::: "memory");
    }
}

extern "C" void kernel_launch(void* const* d_in, const int* in_sizes, int n_in,
                              void* d_out, int out_size)
{
    const float* x     = (const float*)d_in[0];  // [B,5]
    const float* a     = (const float*)d_in[1];  // [B,2]
    const float* noise = (const float*)d_in[2];  // [B,2]
    const float* pg    = (const float*)d_in[3];  // [2]
    const float* pv    = (const float*)d_in[4];  // [2]
    const float* gr    = (const float*)d_in[5];  // [1]

    const int B = in_sizes[0] / 5;               // 8388608 (divisible by 256)
    float* out      = (float*)d_out;             // [B*5] next_x
    float* out_flag = out + (size_t)B * 5;       // [B] reached_target as 0/1 float

    const int blocks = B / ROWS_PER_BLOCK;       // 32768

    Model_72026601554419_kernel<<<blocks, NTHREADS>>>(
        x, (const float2*)a, (const float2*)noise, pg, pv, gr, out, out_flag);
}